// round 12
// baseline (speedup 1.0000x reference)
#include <cuda_runtime.h>

// SymmetryConstraint: closed-form per-class moment reduction + deterministic
// fixed-point integer REDG accumulation across batches.
//
// Per (batch b, class k in {0,1,2}) with m points, u = x-0.5:
//   pair-loss sum = (m-2)*Su2 + Su^2 + m*Sy2 - Sy^2   (>= 0, exactly 0 for m<=1)
//   pair count    = m(m-1)/2
// result = total_loss / max(total_count, 1)
//
// Shape chosen from a 7-variant sweep (grid {64,128,256} x block {128,256,512},
// multiple reduce/tail structures): all land within 6.88-7.33us kernel time
// (launch/drain overhead floor ~5.5-6us dominates); this variant measured the
// best end-to-end (8.576us).

#define BATCH   256
#define NPTS    512
#define THREADS 128

__device__ unsigned long long g_loss_fix = 0ULL;
__device__ unsigned long long g_cnt_fix  = 0ULL;
__device__ unsigned int       g_done     = 0u;

#define LOSS_SCALE 33554432.0f   // 2^25

__global__ __launch_bounds__(THREADS)
void symmetry_kernel(const float4* __restrict__ kp4,
                     const int2*   __restrict__ cls2,
                     float* __restrict__ out)
{
    const int b    = blockIdx.x;
    const int tid  = threadIdx.x;
    const int lane = tid & 31;
    const int wid  = tid >> 5;

    // Each float4 = 2 points (x0,y0,x1,y1); 512 pts = 256 float4 per batch.
    // Thread tid handles float4 slots {tid, tid+128} -> 4 points, with
    // matching int2 class slots {tid, tid+128}.
    const float4* kb = kp4  + (size_t)b * (NPTS / 2);
    const int2*   cb = cls2 + (size_t)b * (NPTS / 2);

    float4 p0 = kb[tid];
    float4 p1 = kb[tid + THREADS];
    int2   c0 = cb[tid];
    int2   c1 = cb[tid + THREADS];

    // 3 classes x {m, Su, Su2, Sy, Sy2}
    float acc[15];
#pragma unroll
    for (int i = 0; i < 15; i++) acc[i] = 0.f;

    float px[4] = { p0.x, p0.z, p1.x, p1.z };
    float py[4] = { p0.y, p0.w, p1.y, p1.w };
    int   pc[4] = { c0.x, c0.y, c1.x, c1.y };

#pragma unroll
    for (int j = 0; j < 4; j++) {
        float u = px[j] - 0.5f;
        float y = py[j];
        int   ci = pc[j];
#pragma unroll
        for (int k = 0; k < 3; k++) {
            float w = (ci == k) ? 1.f : 0.f;
            acc[k * 5 + 0] += w;
            acc[k * 5 + 1] += w * u;
            acc[k * 5 + 2] += w * u * u;
            acc[k * 5 + 3] += w * y;
            acc[k * 5 + 4] += w * y * y;
        }
    }

    // warp reduce 15 independent values
#pragma unroll
    for (int i = 0; i < 15; i++) {
#pragma unroll
        for (int off = 16; off; off >>= 1)
            acc[i] += __shfl_down_sync(0xffffffffu, acc[i], off);
    }

    __shared__ float smem[THREADS / 32][15];
    if (lane == 0) {
#pragma unroll
        for (int i = 0; i < 15; i++) smem[wid][i] = acc[i];
    }
    __syncthreads();

    if (tid == 0) {
        float loss = 0.f, cnt = 0.f;
#pragma unroll
        for (int k = 0; k < 3; k++) {
            float m = 0.f, su = 0.f, su2 = 0.f, sy = 0.f, sy2 = 0.f;
#pragma unroll
            for (int w = 0; w < THREADS / 32; w++) {
                m   += smem[w][k * 5 + 0];
                su  += smem[w][k * 5 + 1];
                su2 += smem[w][k * 5 + 2];
                sy  += smem[w][k * 5 + 3];
                sy2 += smem[w][k * 5 + 4];
            }
            loss += (m - 2.f) * su2 + su * su + m * sy2 - sy * sy;
            cnt  += 0.5f * m * (m - 1.f);   // exact: m integer-valued < 2^12
        }
        // loss >= 0 mathematically; clamp tiny negative rounding residue
        loss = fmaxf(loss, 0.f);

        // deterministic integer accumulation (REDG, order-independent)
        unsigned long long lfix = (unsigned long long)(loss * LOSS_SCALE + 0.5f);
        unsigned long long cfix = (unsigned long long)(cnt + 0.5f);
        atomicAdd(&g_loss_fix, lfix);
        atomicAdd(&g_cnt_fix,  cfix);
        __threadfence();

        if (atomicAdd(&g_done, 1u) == BATCH - 1) {
            // last block: all REDGs are globally visible (fence before counter)
            unsigned long long L = atomicAdd(&g_loss_fix, 0ULL);
            unsigned long long C = atomicAdd(&g_cnt_fix,  0ULL);
            double total = (double)L * (1.0 / 33554432.0);
            double denom = (C > 0ULL) ? (double)C : 1.0;
            out[0] = (float)(total / denom);
            // reset for next graph replay (ordered by kernel completion)
            g_loss_fix = 0ULL;
            g_cnt_fix  = 0ULL;
            g_done     = 0u;
            __threadfence();
        }
    }
}

extern "C" void kernel_launch(void* const* d_in, const int* in_sizes, int n_in,
                              void* d_out, int out_size)
{
    const float4* kp4  = (const float4*)d_in[0];  // [256, 512, 2] f32
    const int2*   cls2 = (const int2*)d_in[1];    // [256, 512] i32
    float*        out  = (float*)d_out;           // [1] f32
    symmetry_kernel<<<BATCH, THREADS>>>(kp4, cls2, out);
}

// round 13
// speedup vs baseline: 1.2079x; 1.2079x over previous
#include <cuda_runtime.h>

// SymmetryConstraint — final kernel (minimum-variance configuration).
//
// Closed form per (batch, class k in {0,1,2}), m points of class k, u = x-0.5:
//   pair-loss sum = (m-2)*Su2 + Su^2 + m*Sy2 - Sy^2   (>= 0, 0 for m<=1)
//   pair count    = m(m-1)/2
// result = total_loss / max(total_count, 1)
//
// Measurement history: 8-variant sweep over grid {64,128,256} x block
// {128,256,512} and multiple reduce/tail structures; kernel time band
// 6.88-8.67us, e2e 8.58-10.78us, with a byte-identical kernel measuring
// 8.58 and 10.78 in different rounds (run-to-run noise +-1-2us >> any
// inter-variant delta). Duration is launch/distribution/drain overhead
// (~5.5-6us) at microburst DVFS clocks; all pipes <4%. This 256x256 shape
// reproduced e2e 8.704us in 4/4 independent rounds — best repeatability.

#define BATCH   256
#define NPTS    512
#define THREADS 256
#define NWARP   (THREADS / 32)   // 8

__device__ unsigned long long g_loss_fix = 0ULL;
__device__ unsigned long long g_cnt_fix  = 0ULL;
__device__ unsigned int       g_done     = 0u;

#define LOSS_SCALE 33554432.0f   // 2^25

__global__ __launch_bounds__(THREADS)
void symmetry_kernel(const float4* __restrict__ kp4,
                     const int2*   __restrict__ cls2,
                     float* __restrict__ out)
{
    const int b    = blockIdx.x;
    const int tid  = threadIdx.x;
    const int lane = tid & 31;
    const int wid  = tid >> 5;

    // 256 float4 (2 pts each) + 256 int2 per batch; one of each per thread.
    float4 p = kp4 [(size_t)b * (NPTS / 2) + tid];
    int2   c = cls2[(size_t)b * (NPTS / 2) + tid];

    // 3 classes x {Su, Su2, Sy, Sy2} in float (fma pipe); counts in int (alu pipe).
    float fa[12];
#pragma unroll
    for (int i = 0; i < 12; i++) fa[i] = 0.f;
    int m0 = 0, m1 = 0, m2 = 0;

    float ux[2] = { p.x - 0.5f, p.z - 0.5f };
    float yy[2] = { p.y,        p.w        };
    int   cc[2] = { c.x,        c.y        };

#pragma unroll
    for (int t = 0; t < 2; t++) {
        float u = ux[t], y = yy[t];
        int ci = cc[t];
        m0 += (ci == 0);
        m1 += (ci == 1);
        m2 += (ci == 2);
#pragma unroll
        for (int k = 0; k < 3; k++) {
            float w = (ci == k) ? 1.f : 0.f;
            fa[k * 4 + 0] += w * u;
            fa[k * 4 + 1] += w * u * u;
            fa[k * 4 + 2] += w * y;
            fa[k * 4 + 3] += w * y * y;
        }
    }

    // warp reduce: 12 independent floats (pipelined shuffle stages) + 3 REDUX
#pragma unroll
    for (int off = 16; off; off >>= 1) {
#pragma unroll
        for (int i = 0; i < 12; i++)
            fa[i] += __shfl_down_sync(0xffffffffu, fa[i], off);
    }
    m0 = __reduce_add_sync(0xffffffffu, m0);
    m1 = __reduce_add_sync(0xffffffffu, m1);
    m2 = __reduce_add_sync(0xffffffffu, m2);

    __shared__ float s_mom[NWARP][16];   // 15 used, padded row
    if (lane == 0) {
#pragma unroll
        for (int i = 0; i < 12; i++) s_mom[wid][i] = fa[i];
        s_mom[wid][12] = (float)m0;
        s_mom[wid][13] = (float)m1;
        s_mom[wid][14] = (float)m2;
    }
    __syncthreads();

    if (wid == 0) {
        // lanes 0..14 each sum one quantity across the 8 warps (parallel)
        float s = 0.f;
        if (lane < 15) {
#pragma unroll
            for (int w = 0; w < NWARP; w++) s += s_mom[w][lane];
        }
        float tot[15];
#pragma unroll
        for (int i = 0; i < 15; i++)
            tot[i] = __shfl_sync(0xffffffffu, s, i);

        if (lane == 0) {
            float loss = 0.f, cnt = 0.f;
#pragma unroll
            for (int k = 0; k < 3; k++) {
                float su  = tot[k * 4 + 0];
                float su2 = tot[k * 4 + 1];
                float sy  = tot[k * 4 + 2];
                float sy2 = tot[k * 4 + 3];
                float m   = tot[12 + k];
                loss += (m - 2.f) * su2 + su * su + m * sy2 - sy * sy;
                cnt  += 0.5f * m * (m - 1.f);   // exact: m integer < 2^10
            }
            loss = fmaxf(loss, 0.f);

            // deterministic order-independent integer accumulation (relaxed)
            unsigned long long lfix = (unsigned long long)(loss * LOSS_SCALE + 0.5f);
            unsigned long long cfix = (unsigned long long)(cnt + 0.5f);
            atomicAdd(&g_loss_fix, lfix);
            atomicAdd(&g_cnt_fix,  cfix);

            // acq_rel counter: release orders our adds; acquire makes all
            // 256 contributions visible to whoever observes prev == BATCH-1.
            unsigned int prev;
            asm volatile("atom.add.acq_rel.gpu.global.u32 %0, [%1], 1;"
                         : "=r"(prev) : "l"(&g_done) : "memory");

            if (prev == BATCH - 1) {
                unsigned long long L, C;
                asm volatile("ld.acquire.gpu.global.u64 %0, [%1];"
                             : "=l"(L) : "l"(&g_loss_fix) : "memory");
                asm volatile("ld.acquire.gpu.global.u64 %0, [%1];"
                             : "=l"(C) : "l"(&g_cnt_fix) : "memory");
                double total = (double)L * (1.0 / 33554432.0);
                double denom = (C > 0ULL) ? (double)C : 1.0;
                out[0] = (float)(total / denom);
                // reset for next graph replay (ordered by kernel boundary)
                g_loss_fix = 0ULL;
                g_cnt_fix  = 0ULL;
                g_done     = 0u;
            }
        }
    }
}

extern "C" void kernel_launch(void* const* d_in, const int* in_sizes, int n_in,
                              void* d_out, int out_size)
{
    const float4* kp4  = (const float4*)d_in[0];  // [256, 512, 2] f32
    const int2*   cls2 = (const int2*)d_in[1];    // [256, 512] i32
    float*        out  = (float*)d_out;           // [1] f32
    symmetry_kernel<<<BATCH, THREADS>>>(kp4, cls2, out);
}

// round 15
// speedup vs baseline: 1.2962x; 1.0731x over previous
#include <cuda_runtime.h>

// SymmetryConstraint — FINAL kernel (minimum-variance configuration).
//
// Closed form per (batch, class k in {0,1,2}), m points of class k, u = x-0.5:
//   pair-loss sum = (m-2)*Su2 + Su^2 + m*Sy2 - Sy^2   (>= 0, 0 for m<=1)
//   pair count    = m(m-1)/2
// result = total_loss / max(total_count, 1)
//
// The formula's cross terms (Su^2, m*Su2, ...) are products of per-batch
// sums, so block-per-batch + nonlinear combine + tiny global tail is the
// algorithmic minimum (one pass over 1.5 MB).
//
// Measurement record (9 rounds): kernel 6.88-8.67us, e2e 8.58-10.78us across
// grid {64,128,256} x block {128,256,512} and 6 reduce/tail structures; a
// byte-identical kernel measured 8.58 and 10.78 in different rounds, so
// run-to-run noise (+-1-2us, DVFS/microburst) dominates all variant deltas.
// Duration = ~5.5-6us launch/distribution/drain overhead + <1.5us work
// (all pipes <4%). This 256x256 shape: e2e mode 8.704us (4/6 samples),
// best repeatability -> committed as final.

#define BATCH   256
#define NPTS    512
#define THREADS 256
#define NWARP   (THREADS / 32)   // 8

__device__ unsigned long long g_loss_fix = 0ULL;
__device__ unsigned long long g_cnt_fix  = 0ULL;
__device__ unsigned int       g_done     = 0u;

#define LOSS_SCALE 33554432.0f   // 2^25

__global__ __launch_bounds__(THREADS)
void symmetry_kernel(const float4* __restrict__ kp4,
                     const int2*   __restrict__ cls2,
                     float* __restrict__ out)
{
    const int b    = blockIdx.x;
    const int tid  = threadIdx.x;
    const int lane = tid & 31;
    const int wid  = tid >> 5;

    // 256 float4 (2 pts each) + 256 int2 per batch; one of each per thread.
    float4 p = kp4 [(size_t)b * (NPTS / 2) + tid];
    int2   c = cls2[(size_t)b * (NPTS / 2) + tid];

    // 3 classes x {Su, Su2, Sy, Sy2} in float (fma pipe); counts in int (alu pipe).
    float fa[12];
#pragma unroll
    for (int i = 0; i < 12; i++) fa[i] = 0.f;
    int m0 = 0, m1 = 0, m2 = 0;

    float ux[2] = { p.x - 0.5f, p.z - 0.5f };
    float yy[2] = { p.y,        p.w        };
    int   cc[2] = { c.x,        c.y        };

#pragma unroll
    for (int t = 0; t < 2; t++) {
        float u = ux[t], y = yy[t];
        int ci = cc[t];
        m0 += (ci == 0);
        m1 += (ci == 1);
        m2 += (ci == 2);
#pragma unroll
        for (int k = 0; k < 3; k++) {
            float w = (ci == k) ? 1.f : 0.f;
            fa[k * 4 + 0] += w * u;
            fa[k * 4 + 1] += w * u * u;
            fa[k * 4 + 2] += w * y;
            fa[k * 4 + 3] += w * y * y;
        }
    }

    // warp reduce: 12 independent floats (pipelined shuffle stages) + 3 REDUX
#pragma unroll
    for (int off = 16; off; off >>= 1) {
#pragma unroll
        for (int i = 0; i < 12; i++)
            fa[i] += __shfl_down_sync(0xffffffffu, fa[i], off);
    }
    m0 = __reduce_add_sync(0xffffffffu, m0);
    m1 = __reduce_add_sync(0xffffffffu, m1);
    m2 = __reduce_add_sync(0xffffffffu, m2);

    __shared__ float s_mom[NWARP][16];   // 15 used, padded row
    if (lane == 0) {
#pragma unroll
        for (int i = 0; i < 12; i++) s_mom[wid][i] = fa[i];
        s_mom[wid][12] = (float)m0;
        s_mom[wid][13] = (float)m1;
        s_mom[wid][14] = (float)m2;
    }
    __syncthreads();

    if (wid == 0) {
        // lanes 0..14 each sum one quantity across the 8 warps (parallel)
        float s = 0.f;
        if (lane < 15) {
#pragma unroll
            for (int w = 0; w < NWARP; w++) s += s_mom[w][lane];
        }
        float tot[15];
#pragma unroll
        for (int i = 0; i < 15; i++)
            tot[i] = __shfl_sync(0xffffffffu, s, i);

        if (lane == 0) {
            float loss = 0.f, cnt = 0.f;
#pragma unroll
            for (int k = 0; k < 3; k++) {
                float su  = tot[k * 4 + 0];
                float su2 = tot[k * 4 + 1];
                float sy  = tot[k * 4 + 2];
                float sy2 = tot[k * 4 + 3];
                float m   = tot[12 + k];
                loss += (m - 2.f) * su2 + su * su + m * sy2 - sy * sy;
                cnt  += 0.5f * m * (m - 1.f);   // exact: m integer < 2^10
            }
            loss = fmaxf(loss, 0.f);

            // deterministic order-independent integer accumulation (relaxed)
            unsigned long long lfix = (unsigned long long)(loss * LOSS_SCALE + 0.5f);
            unsigned long long cfix = (unsigned long long)(cnt + 0.5f);
            atomicAdd(&g_loss_fix, lfix);
            atomicAdd(&g_cnt_fix,  cfix);

            // acq_rel counter: release orders our adds; acquire makes all
            // 256 contributions visible to whoever observes prev == BATCH-1.
            unsigned int prev;
            asm volatile("atom.add.acq_rel.gpu.global.u32 %0, [%1], 1;"
                         : "=r"(prev) : "l"(&g_done) : "memory");

            if (prev == BATCH - 1) {
                unsigned long long L, C;
                asm volatile("ld.acquire.gpu.global.u64 %0, [%1];"
                             : "=l"(L) : "l"(&g_loss_fix) : "memory");
                asm volatile("ld.acquire.gpu.global.u64 %0, [%1];"
                             : "=l"(C) : "l"(&g_cnt_fix) : "memory");
                double total = (double)L * (1.0 / 33554432.0);
                double denom = (C > 0ULL) ? (double)C : 1.0;
                out[0] = (float)(total / denom);
                // reset for next graph replay (ordered by kernel boundary)
                g_loss_fix = 0ULL;
                g_cnt_fix  = 0ULL;
                g_done     = 0u;
            }
        }
    }
}

extern "C" void kernel_launch(void* const* d_in, const int* in_sizes, int n_in,
                              void* d_out, int out_size)
{
    const float4* kp4  = (const float4*)d_in[0];  // [256, 512, 2] f32
    const int2*   cls2 = (const int2*)d_in[1];    // [256, 512] i32
    float*        out  = (float*)d_out;           // [1] f32
    symmetry_kernel<<<BATCH, THREADS>>>(kp4, cls2, out);
}